// round 14
// baseline (speedup 1.0000x reference)
#include <cuda_runtime.h>
#include <cuda_fp16.h>
#include <cstdint>

#define NTOK 16384
#define BDIM 8
#define LSEQ 2048
#define DM   512
#define HID  1024
#define NTOT 2048   // 2*HID
#define NCH  16     // scan chunks per chain
#define CL   (LSEQ / NCH)   // 128

// ---------------------------------------------------------------------------
// Device-global scratch (allocation-free)
// ---------------------------------------------------------------------------
__device__ __half g_Xh [(size_t)NTOK * DM];
__device__ __half g_W1h[(size_t)NTOT * DM];
__device__ __half g_Woh[(size_t)DM * NTOT];
__device__ __half g_Hh [(size_t)NTOK * NTOT];
__device__ float  g_y  [(size_t)NTOK * DM];
__device__ float  g_lre[HID], g_lim[HID];
__device__ float  g_gamI[NTOT], g_bgI[NTOT];   // interleaved gamma / bias*gamma
__device__ float2 g_endl[BDIM * NCH * HID];    // chunk-local end state
__device__ float2 g_T   [BDIM * NCH * HID];    // chunk transfer coefficient

// ---------------------------------------------------------------------------
// fp16 conversion pre-passes
// ---------------------------------------------------------------------------
__global__ void cvt_x_kernel(const float* __restrict__ x) {
    int i = blockIdx.x * 256 + threadIdx.x;        // NTOK*DM/4 threads
    float4 v = reinterpret_cast<const float4*>(x)[i];
    __half2* out = reinterpret_cast<__half2*>(g_Xh) + 2 * i;
    out[0] = __floats2half2_rn(v.x, v.y);
    out[1] = __floats2half2_rn(v.z, v.w);
}

// Merged weight conversion + precompute.
__global__ void cvt_wp_kernel(const float* __restrict__ Wre, const float* __restrict__ Wim,
                              const float* __restrict__ Wor, const float* __restrict__ Woi,
                              const float* __restrict__ plog,
                              const float* __restrict__ bre, const float* __restrict__ bim) {
    if (blockIdx.x < 512) {
        int i = blockIdx.x * 256 + threadIdx.x;    // HID*DM/4 threads
        int h  = i >> 7;
        int kq = i & 127;
        float4 a = reinterpret_cast<const float4*>(Wre)[i];
        float4 b = reinterpret_cast<const float4*>(Wim)[i];
        __half2* outA = reinterpret_cast<__half2*>(g_W1h + (size_t)(2 * h) * DM + 4 * kq);
        __half2* outB = reinterpret_cast<__half2*>(g_W1h + (size_t)(2 * h + 1) * DM + 4 * kq);
        outA[0] = __floats2half2_rn(a.x, a.y);
        outA[1] = __floats2half2_rn(a.z, a.w);
        outB[0] = __floats2half2_rn(b.x, b.y);
        outB[1] = __floats2half2_rn(b.z, b.w);
    } else if (blockIdx.x < 1024) {
        int i = (blockIdx.x - 512) * 256 + threadIdx.x;  // DM*HID/4 threads
        int d  = i >> 8;
        int hq = i & 255;
        float4 a = reinterpret_cast<const float4*>(Wor)[i];
        float4 b = reinterpret_cast<const float4*>(Woi)[i];
        __half2* out = reinterpret_cast<__half2*>(g_Woh + (size_t)d * NTOT + 8 * hq);
        out[0] = __floats2half2_rn(a.x, -b.x);
        out[1] = __floats2half2_rn(a.y, -b.y);
        out[2] = __floats2half2_rn(a.z, -b.z);
        out[3] = __floats2half2_rn(a.w, -b.w);
    } else {
#pragma unroll
        for (int i = 0; i < 4; i++) {
            int h = threadIdx.x + 256 * i;
            float nu = expf(plog[h]);
            float th = expf(plog[HID + h]);
            float ga = expf(plog[2 * HID + h]);
            float er = expf(-nu);
            g_lre[h] = er * cosf(th);
            g_lim[h] = er * sinf(th);
            g_gamI[2 * h] = ga;  g_gamI[2 * h + 1] = ga;
            g_bgI[2 * h] = bre[h] * ga;  g_bgI[2 * h + 1] = bim[h] * ga;
        }
    }
}

// ---------------------------------------------------------------------------
// fp16 tensor-core GEMM (see header comment in theory above).
// MODE 1: aux = mask pointer (fused scan phase 1). MODE 2: aux = bias.
// ---------------------------------------------------------------------------
__device__ __forceinline__ void cp16(uint32_t dst, const __half* src) {
    asm volatile("cp.async.cg.shared.global [%0], [%1], 16;" :: "r"(dst), "l"(src));
}

#define LDSM4(R0, R1, R2, R3, addr) \
    asm volatile("ldmatrix.sync.aligned.m8n8.x4.shared.b16 {%0,%1,%2,%3}, [%4];" \
                 : "=r"(R0), "=r"(R1), "=r"(R2), "=r"(R3) : "r"(addr))

#define MMA_F16(c, a, b0r, b1r) \
    asm volatile("mma.sync.aligned.m16n8k16.row.col.f32.f16.f16.f32 " \
                 "{%0,%1,%2,%3}, {%4,%5,%6,%7}, {%8,%9}, {%0,%1,%2,%3};" \
                 : "+f"(c[0]), "+f"(c[1]), "+f"(c[2]), "+f"(c[3]) \
                 : "r"(a[0]), "r"(a[1]), "r"(a[2]), "r"(a[3]), "r"(b0r), "r"(b1r))

template<int K, int MODE>
__global__ __launch_bounds__(128, 2)
void gemm_f16(const float* __restrict__ aux, const float* __restrict__ resid) {
    extern __shared__ char smem[];
    const __half* A    = (MODE == 1) ? g_Xh  : g_Hh;
    const __half* Bmat = (MODE == 1) ? g_W1h : g_Woh;

    constexpr int ABYTES = 16384;
    constexpr int BBYTES = 16384;
    constexpr int NJ = 8;

    const int tid  = threadIdx.x;
    const int lane = tid & 31;
    const int wid  = tid >> 5;
    const int wm   = (wid >> 1) * 64;
    const int wn   = (wid & 1) * 64;
    const int bm   = blockIdx.x * 128;
    const int bn   = blockIdx.y * 128;

    uint32_t sm_base = (uint32_t)__cvta_generic_to_shared(smem);
    uint32_t sA0 = sm_base;
    uint32_t sB0 = sm_base + 3 * ABYTES;

    float acc[4][NJ][4];
#pragma unroll
    for (int i = 0; i < 4; i++)
#pragma unroll
        for (int j = 0; j < NJ; j++)
#pragma unroll
            for (int e = 0; e < 4; e++) acc[i][j][e] = 0.f;

    constexpr int KT = K / 64;

    auto load_tile = [&](int s, int k0) {
#pragma unroll
        for (int i = 0; i < 8; i++) {
            int ch = tid + (i << 7);
            int r  = ch >> 3;
            int c  = ch & 7;
            uint32_t off = (uint32_t)(r * 128 + ((c ^ (r & 7)) << 4));
            cp16(sA0 + s * ABYTES + off, A    + (size_t)(bm + r) * K + k0 + (c << 3));
            cp16(sB0 + s * BBYTES + off, Bmat + (size_t)(bn + r) * K + k0 + (c << 3));
        }
    };

    load_tile(0, 0);
    asm volatile("cp.async.commit_group;" ::: "memory");
    load_tile(1, 64);
    asm volatile("cp.async.commit_group;" ::: "memory");

    const int rb  = (lane & 7) + ((lane >> 3) & 1) * 8;
    const int chi = lane >> 4;

    for (int kt = 0; kt < KT; kt++) {
        int s = kt % 3;
        asm volatile("cp.async.wait_group 1;" ::: "memory");
        __syncthreads();

        int kn = kt + 2;
        if (kn < KT) load_tile(kn % 3, kn * 64);
        asm volatile("cp.async.commit_group;" ::: "memory");

        uint32_t sa = sA0 + s * ABYTES;
        uint32_t sb = sB0 + s * BBYTES;
#pragma unroll
        for (int kk = 0; kk < 4; kk++) {
            uint32_t af[4][4];
#pragma unroll
            for (int mi = 0; mi < 4; mi++) {
                int r = wm + (mi << 4) + rb;
                int c = (kk << 1) + chi;
                LDSM4(af[mi][0], af[mi][1], af[mi][2], af[mi][3],
                      sa + r * 128 + ((c ^ (r & 7)) << 4));
            }
            uint32_t bf[4][4];
#pragma unroll
            for (int jj = 0; jj < 4; jj++) {
                int r = wn + (jj << 4) + rb;
                int c = (kk << 1) + chi;
                LDSM4(bf[jj][0], bf[jj][1], bf[jj][2], bf[jj][3],
                      sb + r * 128 + ((c ^ (r & 7)) << 4));
            }
#pragma unroll
            for (int mi = 0; mi < 4; mi++)
#pragma unroll
                for (int nj = 0; nj < NJ; nj++)
                    MMA_F16(acc[mi][nj], af[mi],
                            bf[nj >> 1][nj & 1], bf[nj >> 1][2 + (nj & 1)]);
        }
    }

    const int gid = lane >> 2, tig = lane & 3;

    if (MODE == 1) {
        // Reuse pipeline smem: su[row][ch] (128x64 u-values as half2 bits,
        // 32KB) + smask[128]. One sync guards reuse after the mainloop.
        uint32_t* su    = reinterpret_cast<uint32_t*>(smem);
        float*    smask = reinterpret_cast<float*>(smem + 32768);
        const int b = bm >> 11;
        const int l0 = bm & (LSEQ - 1);
        __syncthreads();

        {
            int gl = l0 + tid - 1;
            smask[tid] = (gl >= 0) ? aux[b * LSEQ + gl] : 0.f;
        }

#pragma unroll
        for (int nj = 0; nj < NJ; nj++) {
            int nl = wn + (nj << 3) + (tig << 1);   // local even column
            int n0 = bn + nl;
            float g0 = g_gamI[n0], g1 = g_gamI[n0 + 1];
            float q0 = g_bgI[n0],  q1 = g_bgI[n0 + 1];
            int chL = nl >> 1;                       // local complex channel
#pragma unroll
            for (int mi = 0; mi < 4; mi++) {
                int rl0 = wm + (mi << 4) + gid;      // local row
                int m0 = bm + rl0;
                __half2 v0 = __floats2half2_rn(fmaf(acc[mi][nj][0], g0, q0),
                                               fmaf(acc[mi][nj][1], g1, q1));
                __half2 v1 = __floats2half2_rn(fmaf(acc[mi][nj][2], g0, q0),
                                               fmaf(acc[mi][nj][3], g1, q1));
                *reinterpret_cast<__half2*>(&g_Hh[(size_t)m0 * NTOT + n0]) = v0;
                *reinterpret_cast<__half2*>(&g_Hh[(size_t)(m0 + 8) * NTOT + n0]) = v1;
                su[rl0 * 64 + chL]       = *reinterpret_cast<uint32_t*>(&v0);
                su[(rl0 + 8) * 64 + chL] = *reinterpret_cast<uint32_t*>(&v1);
            }
        }
        __syncthreads();

        // fused scan phase 1: 64 threads, one complex channel, 128 rows
        if (tid < 64) {
            int gch = (bn >> 1) + tid;
            float lre_ = g_lre[gch], lim_ = g_lim[gch];
            float px = 0.f, py = 0.f, Tx = 1.f, Ty = 0.f;
#pragma unroll 8
            for (int row = 0; row < 128; row++) {
                uint32_t ub = su[row * 64 + tid];
                float2 u = __half22float2(*reinterpret_cast<__half2*>(&ub));
                float m = smask[row];
                float fr = lre_ * m, fi = lim_ * m;
                float r  = u.x + fr * px - fi * py;
                float im = u.y + fr * py + fi * px;
                px = r; py = im;
                float tr = fr * Tx - fi * Ty;
                float ti = fr * Ty + fi * Tx;
                Tx = tr; Ty = ti;
            }
            int c = (bm >> 7) & (NCH - 1);
            int o = (b * NCH + c) * HID + gch;
            g_endl[o] = make_float2(px, py);
            g_T[o]    = make_float2(Tx, Ty);
        }
    } else {
#pragma unroll
        for (int nj = 0; nj < NJ; nj++) {
            int n0 = bn + wn + (nj << 3) + (tig << 1);
            float b0 = aux[n0], b1 = aux[n0 + 1];
#pragma unroll
            for (int mi = 0; mi < 4; mi++) {
                int m0 = bm + wm + (mi << 4) + gid;
                float2 x0 = *reinterpret_cast<const float2*>(&resid[(size_t)m0 * DM + n0]);
                float2 x1 = *reinterpret_cast<const float2*>(&resid[(size_t)(m0 + 8) * DM + n0]);
                float2 v0 = make_float2(acc[mi][nj][0] + b0 + x0.x,
                                        acc[mi][nj][1] + b1 + x0.y);
                float2 v1 = make_float2(acc[mi][nj][2] + b0 + x1.x,
                                        acc[mi][nj][3] + b1 + x1.y);
                *reinterpret_cast<float2*>(&g_y[(size_t)m0 * DM + n0]) = v0;
                *reinterpret_cast<float2*>(&g_y[(size_t)(m0 + 8) * DM + n0]) = v1;
            }
        }
    }
}

// ---------------------------------------------------------------------------
// Scan phase 2 with inline lookback.
// ---------------------------------------------------------------------------
__global__ void scan_phase2(const float* __restrict__ mask) {
    __shared__ float ms[CL];
    const int bid = blockIdx.x;
    const int b  = bid >> 7;
    const int c  = (bid >> 3) & (NCH - 1);
    const int hb = bid & 7;
    const int h  = hb * 128 + threadIdx.x;
    const int l0 = c * CL;

    {
        int gl = l0 + threadIdx.x - 1;
        ms[threadIdx.x] = (gl >= 0) ? mask[b * LSEQ + gl] : 0.f;
    }

    float2 prev = make_float2(0.f, 0.f);
    for (int cc = 0; cc < c; cc++) {
        int o = (b * NCH + cc) * HID + h;
        float2 e = g_endl[o];
        float2 t = g_T[o];
        float r  = e.x + t.x * prev.x - t.y * prev.y;
        float im = e.y + t.x * prev.y + t.y * prev.x;
        prev.x = r; prev.y = im;
    }
    __syncthreads();

    const float lre = g_lre[h], lim = g_lim[h];
    __half2* p = reinterpret_cast<__half2*>(g_Hh)
               + (size_t)b * LSEQ * (NTOT / 2) + (size_t)l0 * (NTOT / 2) + h;
    const int S = NTOT / 2;

    const int U = 8;
    float2 nv[U];
#pragma unroll
    for (int j = 0; j < U; j++) nv[j] = __half22float2(p[(size_t)j * S]);

    for (int j0 = 0; j0 < CL; j0 += U) {
        float2 cv[U];
#pragma unroll
        for (int j = 0; j < U; j++) cv[j] = nv[j];
        if (j0 + U < CL) {
#pragma unroll
            for (int j = 0; j < U; j++)
                nv[j] = __half22float2(p[(size_t)(j0 + U + j) * S]);
        }
#pragma unroll
        for (int j = 0; j < U; j++) {
            int l = l0 + j0 + j;
            if (l > 0) {
                float m = ms[j0 + j];
                float fr = lre * m, fi = lim * m;
                float r  = cv[j].x + fr * prev.x - fi * prev.y;
                float im = cv[j].y + fr * prev.y + fi * prev.x;
                prev.x = r; prev.y = im;
            } else {
                prev = cv[j];
            }
            p[(size_t)(j0 + j) * S] = __floats2half2_rn(prev.x, prev.y);
        }
    }
}

// ---------------------------------------------------------------------------
__global__ void ln_kernel(const float* __restrict__ lnw, const float* __restrict__ lnb,
                          float* __restrict__ out) {
    int row = blockIdx.x * 8 + (threadIdx.x >> 5);
    int lane = threadIdx.x & 31;
    const float* yr = g_y + (size_t)row * DM;
    float v[16];
    float s = 0.f;
#pragma unroll
    for (int i = 0; i < 16; i++) { v[i] = yr[lane + 32 * i]; s += v[i]; }
#pragma unroll
    for (int o = 16; o > 0; o >>= 1) s += __shfl_xor_sync(0xffffffffu, s, o);
    float mean = s * (1.0f / DM);
    float q = 0.f;
#pragma unroll
    for (int i = 0; i < 16; i++) { float d = v[i] - mean; q = fmaf(d, d, q); }
#pragma unroll
    for (int o = 16; o > 0; o >>= 1) q += __shfl_xor_sync(0xffffffffu, q, o);
    float inv = rsqrtf(q * (1.0f / DM) + 1e-5f);
#pragma unroll
    for (int i = 0; i < 16; i++) {
        int c = lane + 32 * i;
        out[(size_t)row * DM + c] = (v[i] - mean) * inv * lnw[c] + lnb[c];
    }
}

// ---------------------------------------------------------------------------
extern "C" void kernel_launch(void* const* d_in, const int* in_sizes, int n_in,
                              void* d_out, int out_size) {
    const float* x    = (const float*)d_in[0];
    const float* mask = (const float*)d_in[1];
    const float* plog = (const float*)d_in[2];
    const float* Wre  = (const float*)d_in[3];
    const float* Wim  = (const float*)d_in[4];
    const float* bre  = (const float*)d_in[5];
    const float* bim  = (const float*)d_in[6];
    const float* Wor  = (const float*)d_in[7];
    const float* Woi  = (const float*)d_in[8];
    const float* bor  = (const float*)d_in[9];
    // d_in[10] = b_out_im (unused: only real part survives)
    const float* lnw  = (const float*)d_in[11];
    const float* lnb  = (const float*)d_in[12];
    float* out = (float*)d_out;

    const int smem1 = 3 * (128 * 128 + 16384);  // 98304
    cudaFuncSetAttribute(gemm_f16<DM, 1>,
                         cudaFuncAttributeMaxDynamicSharedMemorySize, smem1);
    cudaFuncSetAttribute(gemm_f16<NTOT, 2>,
                         cudaFuncAttributeMaxDynamicSharedMemorySize, smem1);

    cvt_x_kernel <<<(NTOK * DM / 4) / 256, 256>>>(x);
    cvt_wp_kernel<<<1025, 256>>>(Wre, Wim, Wor, Woi, plog, bre, bim);

    // GEMM1 + fused scan phase 1 (mask passed via aux slot)
    gemm_f16<DM, 1><<<dim3(NTOK / 128, NTOT / 128), 128, smem1>>>(mask, nullptr);

    // scan phase 2 with inline lookback (capture slot 4)
    scan_phase2<<<BDIM * NCH * 8, 128>>>(mask);

    // GEMM2: y = H @ [Wor,-Woi]^T + b_out_re + x  -> g_y
    gemm_f16<NTOT, 2><<<dim3(NTOK / 128, DM / 128), 128, smem1>>>(bor, x);

    ln_kernel<<<NTOK / 8, 256>>>(lnw, lnb, out);
}

// round 16
// speedup vs baseline: 1.0354x; 1.0354x over previous
#include <cuda_runtime.h>
#include <cuda_fp16.h>
#include <cstdint>

#define NTOK 16384
#define BDIM 8
#define LSEQ 2048
#define DM   512
#define HID  1024
#define NTOT 2048   // 2*HID
#define NCH  16     // scan chunks per chain
#define CL   (LSEQ / NCH)   // 128

// ---------------------------------------------------------------------------
// Device-global scratch (allocation-free)
// ---------------------------------------------------------------------------
__device__ __half g_Xh [(size_t)NTOK * DM];
__device__ __half g_W1h[(size_t)NTOT * DM];
__device__ __half g_Woh[(size_t)DM * NTOT];
__device__ __half g_Hh [(size_t)NTOK * NTOT];
__device__ float  g_y  [(size_t)NTOK * DM];
__device__ float  g_lre[HID], g_lim[HID];
__device__ float  g_gamI[NTOT], g_bgI[NTOT];   // interleaved gamma / bias*gamma
__device__ float2 g_endl[BDIM * NCH * HID];    // chunk aggregate end state
__device__ float2 g_T   [BDIM * NCH * HID];    // chunk transfer coefficient
__device__ int    g_flag[BDIM * NCH * 8];      // publish flags (zeroed per run)

// ---------------------------------------------------------------------------
// Merged conversion + precompute + flag reset.
// Blocks [0, 8192): X -> fp16.
// Blocks [8192, 8704): W1 rows interleaved.
// Blocks [8704, 9216): Wo cols interleaved (with -Woi).
// Block 9216: lambda/gamma precompute + zero scan flags.
// ---------------------------------------------------------------------------
__global__ void cvt_all_kernel(const float* __restrict__ x,
                               const float* __restrict__ Wre, const float* __restrict__ Wim,
                               const float* __restrict__ Wor, const float* __restrict__ Woi,
                               const float* __restrict__ plog,
                               const float* __restrict__ bre, const float* __restrict__ bim) {
    if (blockIdx.x < 8192) {
        int i = blockIdx.x * 256 + threadIdx.x;        // NTOK*DM/4 elements (float4)
        float4 v = reinterpret_cast<const float4*>(x)[i];
        __half2* out = reinterpret_cast<__half2*>(g_Xh) + 2 * i;
        out[0] = __floats2half2_rn(v.x, v.y);
        out[1] = __floats2half2_rn(v.z, v.w);
    } else if (blockIdx.x < 8704) {
        int i = (blockIdx.x - 8192) * 256 + threadIdx.x;  // HID*DM/4
        int h  = i >> 7;
        int kq = i & 127;
        float4 a = reinterpret_cast<const float4*>(Wre)[i];
        float4 b = reinterpret_cast<const float4*>(Wim)[i];
        __half2* outA = reinterpret_cast<__half2*>(g_W1h + (size_t)(2 * h) * DM + 4 * kq);
        __half2* outB = reinterpret_cast<__half2*>(g_W1h + (size_t)(2 * h + 1) * DM + 4 * kq);
        outA[0] = __floats2half2_rn(a.x, a.y);
        outA[1] = __floats2half2_rn(a.z, a.w);
        outB[0] = __floats2half2_rn(b.x, b.y);
        outB[1] = __floats2half2_rn(b.z, b.w);
    } else if (blockIdx.x < 9216) {
        int i = (blockIdx.x - 8704) * 256 + threadIdx.x;  // DM*HID/4
        int d  = i >> 8;
        int hq = i & 255;
        float4 a = reinterpret_cast<const float4*>(Wor)[i];
        float4 b = reinterpret_cast<const float4*>(Woi)[i];
        __half2* out = reinterpret_cast<__half2*>(g_Woh + (size_t)d * NTOT + 8 * hq);
        out[0] = __floats2half2_rn(a.x, -b.x);
        out[1] = __floats2half2_rn(a.y, -b.y);
        out[2] = __floats2half2_rn(a.z, -b.z);
        out[3] = __floats2half2_rn(a.w, -b.w);
    } else {
#pragma unroll
        for (int i = 0; i < 4; i++) {
            int h = threadIdx.x + 256 * i;
            float nu = expf(plog[h]);
            float th = expf(plog[HID + h]);
            float ga = expf(plog[2 * HID + h]);
            float er = expf(-nu);
            g_lre[h] = er * cosf(th);
            g_lim[h] = er * sinf(th);
            g_gamI[2 * h] = ga;  g_gamI[2 * h + 1] = ga;
            g_bgI[2 * h] = bre[h] * ga;  g_bgI[2 * h + 1] = bim[h] * ga;
            g_flag[h] = 0;                     // 1024 flags zeroed
        }
    }
}

// ---------------------------------------------------------------------------
// fp16 tensor-core GEMM: C[m][n] = sum_k A[m][k]*B[n][k]
// Block tile 128x128, BK=64, 3-stage cp.async, 4 warps (2x2) of 64x64.
// MODE 1: A=g_Xh, B=g_W1h -> g_Hh (fp16) fused (acc*gamma + bias*gamma)
// MODE 2: A=g_Hh, B=g_Woh -> g_y (fp32) fused (+bias +residual)
// ---------------------------------------------------------------------------
__device__ __forceinline__ void cp16(uint32_t dst, const __half* src) {
    asm volatile("cp.async.cg.shared.global [%0], [%1], 16;" :: "r"(dst), "l"(src));
}

#define LDSM4(R0, R1, R2, R3, addr) \
    asm volatile("ldmatrix.sync.aligned.m8n8.x4.shared.b16 {%0,%1,%2,%3}, [%4];" \
                 : "=r"(R0), "=r"(R1), "=r"(R2), "=r"(R3) : "r"(addr))

#define MMA_F16(c, a, b0r, b1r) \
    asm volatile("mma.sync.aligned.m16n8k16.row.col.f32.f16.f16.f32 " \
                 "{%0,%1,%2,%3}, {%4,%5,%6,%7}, {%8,%9}, {%0,%1,%2,%3};" \
                 : "+f"(c[0]), "+f"(c[1]), "+f"(c[2]), "+f"(c[3]) \
                 : "r"(a[0]), "r"(a[1]), "r"(a[2]), "r"(a[3]), "r"(b0r), "r"(b1r))

template<int K, int MODE>
__global__ __launch_bounds__(128, 2)
void gemm_f16(const float* __restrict__ bias, const float* __restrict__ resid) {
    extern __shared__ char smem[];
    const __half* A    = (MODE == 1) ? g_Xh  : g_Hh;
    const __half* Bmat = (MODE == 1) ? g_W1h : g_Woh;

    constexpr int ABYTES = 16384;
    constexpr int BBYTES = 16384;
    constexpr int NJ = 8;

    const int tid  = threadIdx.x;
    const int lane = tid & 31;
    const int wid  = tid >> 5;
    const int wm   = (wid >> 1) * 64;
    const int wn   = (wid & 1) * 64;
    const int bm   = blockIdx.x * 128;
    const int bn   = blockIdx.y * 128;

    uint32_t sm_base = (uint32_t)__cvta_generic_to_shared(smem);
    uint32_t sA0 = sm_base;
    uint32_t sB0 = sm_base + 3 * ABYTES;

    float acc[4][NJ][4];
#pragma unroll
    for (int i = 0; i < 4; i++)
#pragma unroll
        for (int j = 0; j < NJ; j++)
#pragma unroll
            for (int e = 0; e < 4; e++) acc[i][j][e] = 0.f;

    constexpr int KT = K / 64;

    auto load_tile = [&](int s, int k0) {
#pragma unroll
        for (int i = 0; i < 8; i++) {
            int ch = tid + (i << 7);
            int r  = ch >> 3;
            int c  = ch & 7;
            uint32_t off = (uint32_t)(r * 128 + ((c ^ (r & 7)) << 4));
            cp16(sA0 + s * ABYTES + off, A    + (size_t)(bm + r) * K + k0 + (c << 3));
            cp16(sB0 + s * BBYTES + off, Bmat + (size_t)(bn + r) * K + k0 + (c << 3));
        }
    };

    load_tile(0, 0);
    asm volatile("cp.async.commit_group;" ::: "memory");
    load_tile(1, 64);
    asm volatile("cp.async.commit_group;" ::: "memory");

    const int rb  = (lane & 7) + ((lane >> 3) & 1) * 8;
    const int chi = lane >> 4;

    for (int kt = 0; kt < KT; kt++) {
        int s = kt % 3;
        asm volatile("cp.async.wait_group 1;" ::: "memory");
        __syncthreads();

        int kn = kt + 2;
        if (kn < KT) load_tile(kn % 3, kn * 64);
        asm volatile("cp.async.commit_group;" ::: "memory");

        uint32_t sa = sA0 + s * ABYTES;
        uint32_t sb = sB0 + s * BBYTES;
#pragma unroll
        for (int kk = 0; kk < 4; kk++) {
            uint32_t af[4][4];
#pragma unroll
            for (int mi = 0; mi < 4; mi++) {
                int r = wm + (mi << 4) + rb;
                int c = (kk << 1) + chi;
                LDSM4(af[mi][0], af[mi][1], af[mi][2], af[mi][3],
                      sa + r * 128 + ((c ^ (r & 7)) << 4));
            }
            uint32_t bf[4][4];
#pragma unroll
            for (int jj = 0; jj < 4; jj++) {
                int r = wn + (jj << 4) + rb;
                int c = (kk << 1) + chi;
                LDSM4(bf[jj][0], bf[jj][1], bf[jj][2], bf[jj][3],
                      sb + r * 128 + ((c ^ (r & 7)) << 4));
            }
#pragma unroll
            for (int mi = 0; mi < 4; mi++)
#pragma unroll
                for (int nj = 0; nj < NJ; nj++)
                    MMA_F16(acc[mi][nj], af[mi],
                            bf[nj >> 1][nj & 1], bf[nj >> 1][2 + (nj & 1)]);
        }
    }

    const int gid = lane >> 2, tig = lane & 3;
#pragma unroll
    for (int nj = 0; nj < NJ; nj++) {
        int n0 = bn + wn + (nj << 3) + (tig << 1);
        if (MODE == 1) {
            float g0 = g_gamI[n0], g1 = g_gamI[n0 + 1];
            float q0 = g_bgI[n0],  q1 = g_bgI[n0 + 1];
#pragma unroll
            for (int mi = 0; mi < 4; mi++) {
                int m0 = bm + wm + (mi << 4) + gid;
                __half2 v0 = __floats2half2_rn(fmaf(acc[mi][nj][0], g0, q0),
                                               fmaf(acc[mi][nj][1], g1, q1));
                __half2 v1 = __floats2half2_rn(fmaf(acc[mi][nj][2], g0, q0),
                                               fmaf(acc[mi][nj][3], g1, q1));
                *reinterpret_cast<__half2*>(&g_Hh[(size_t)m0 * NTOT + n0]) = v0;
                *reinterpret_cast<__half2*>(&g_Hh[(size_t)(m0 + 8) * NTOT + n0]) = v1;
            }
        } else {
            float b0 = bias[n0], b1 = bias[n0 + 1];
#pragma unroll
            for (int mi = 0; mi < 4; mi++) {
                int m0 = bm + wm + (mi << 4) + gid;
                float2 x0 = *reinterpret_cast<const float2*>(&resid[(size_t)m0 * DM + n0]);
                float2 x1 = *reinterpret_cast<const float2*>(&resid[(size_t)(m0 + 8) * DM + n0]);
                float2 v0 = make_float2(acc[mi][nj][0] + b0 + x0.x,
                                        acc[mi][nj][1] + b1 + x0.y);
                float2 v1 = make_float2(acc[mi][nj][2] + b0 + x1.x,
                                        acc[mi][nj][3] + b1 + x1.y);
                *reinterpret_cast<float2*>(&g_y[(size_t)m0 * DM + n0]) = v0;
                *reinterpret_cast<float2*>(&g_y[(size_t)(m0 + 8) * DM + n0]) = v1;
            }
        }
    }
}

// ---------------------------------------------------------------------------
// Single-pass decoupled-lookback LRU scan over g_Hh (fp16, re/im interleaved).
// Block = (b, chunk c, hb): 128 threads = 128 complex channels.
// Pass A: chunk aggregate (endl, T), no stores of locals.
// Publish aggregate + flag; lookback composes carry from predecessors.
// Pass B: re-scan chunk (L2-hot) from carry, writing final h.
// Deadlock-free: publish precedes all waiting. mask[-1]=0 makes l=0 exact.
// ---------------------------------------------------------------------------
__global__ void scan_onepass(const float* __restrict__ mask) {
    __shared__ float ms[CL];
    const int bid = blockIdx.x;          // (b<<7) | (c<<3) | hb
    const int b  = bid >> 7;
    const int c  = (bid >> 3) & (NCH - 1);
    const int hb = bid & 7;
    const int h  = hb * 128 + threadIdx.x;
    const int l0 = c * CL;

    {
        int gl = l0 + threadIdx.x - 1;
        ms[threadIdx.x] = (gl >= 0) ? mask[b * LSEQ + gl] : 0.f;
    }
    __syncthreads();

    const float lre = g_lre[h], lim = g_lim[h];
    __half2* p = reinterpret_cast<__half2*>(g_Hh)
               + (size_t)b * LSEQ * (NTOT / 2) + (size_t)l0 * (NTOT / 2) + h;
    const int S = NTOT / 2;
    const int U = 8;

    // ---- pass A: aggregate (endl, T)
    float px = 0.f, py = 0.f, Tx = 1.f, Ty = 0.f;
    {
        float2 nv[U];
#pragma unroll
        for (int j = 0; j < U; j++) nv[j] = __half22float2(p[(size_t)j * S]);
        for (int j0 = 0; j0 < CL; j0 += U) {
            float2 cv[U];
#pragma unroll
            for (int j = 0; j < U; j++) cv[j] = nv[j];
            if (j0 + U < CL) {
#pragma unroll
                for (int j = 0; j < U; j++)
                    nv[j] = __half22float2(p[(size_t)(j0 + U + j) * S]);
            }
#pragma unroll
            for (int j = 0; j < U; j++) {
                float m = ms[j0 + j];
                float fr = lre * m, fi = lim * m;
                float r  = cv[j].x + fr * px - fi * py;
                float im = cv[j].y + fr * py + fi * px;
                px = r; py = im;
                float tr = fr * Tx - fi * Ty;
                float ti = fr * Ty + fi * Tx;
                Tx = tr; Ty = ti;
            }
        }
    }

    // ---- publish aggregate
    {
        int o = (b * NCH + c) * HID + h;
        g_endl[o] = make_float2(px, py);
        g_T[o]    = make_float2(Tx, Ty);
    }
    __threadfence();
    __syncthreads();
    if (threadIdx.x == 0) atomicExch(&g_flag[bid], 1);

    // ---- lookback: compose carry from chunks 0..c-1
    float2 carry = make_float2(0.f, 0.f);
    for (int cc = 0; cc < c; cc++) {
        int fb = (b << 7) | (cc << 3) | hb;
        if (threadIdx.x == 0) {
            while (atomicAdd(&g_flag[fb], 0) == 0) {}
        }
        __syncthreads();
        __threadfence();
        int o = (b * NCH + cc) * HID + h;
        float2 e = g_endl[o];
        float2 t = g_T[o];
        float r  = e.x + t.x * carry.x - t.y * carry.y;
        float im = e.y + t.x * carry.y + t.y * carry.x;
        carry.x = r; carry.y = im;
    }

    // ---- pass B: re-scan from carry, writing final h (L2-hot re-read)
    px = carry.x; py = carry.y;
    {
        float2 nv[U];
#pragma unroll
        for (int j = 0; j < U; j++) nv[j] = __half22float2(p[(size_t)j * S]);
        for (int j0 = 0; j0 < CL; j0 += U) {
            float2 cv[U];
#pragma unroll
            for (int j = 0; j < U; j++) cv[j] = nv[j];
            if (j0 + U < CL) {
#pragma unroll
                for (int j = 0; j < U; j++)
                    nv[j] = __half22float2(p[(size_t)(j0 + U + j) * S]);
            }
#pragma unroll
            for (int j = 0; j < U; j++) {
                float m = ms[j0 + j];
                float fr = lre * m, fi = lim * m;
                float r  = cv[j].x + fr * px - fi * py;
                float im = cv[j].y + fr * py + fi * px;
                px = r; py = im;
                p[(size_t)(j0 + j) * S] = __floats2half2_rn(r, im);
            }
        }
    }
}

// ---------------------------------------------------------------------------
__global__ void ln_kernel(const float* __restrict__ lnw, const float* __restrict__ lnb,
                          float* __restrict__ out) {
    int row = blockIdx.x * 8 + (threadIdx.x >> 5);
    int lane = threadIdx.x & 31;
    const float* yr = g_y + (size_t)row * DM;
    float v[16];
    float s = 0.f;
#pragma unroll
    for (int i = 0; i < 16; i++) { v[i] = yr[lane + 32 * i]; s += v[i]; }
#pragma unroll
    for (int o = 16; o > 0; o >>= 1) s += __shfl_xor_sync(0xffffffffu, s, o);
    float mean = s * (1.0f / DM);
    float q = 0.f;
#pragma unroll
    for (int i = 0; i < 16; i++) { float d = v[i] - mean; q = fmaf(d, d, q); }
#pragma unroll
    for (int o = 16; o > 0; o >>= 1) q += __shfl_xor_sync(0xffffffffu, q, o);
    float inv = rsqrtf(q * (1.0f / DM) + 1e-5f);
#pragma unroll
    for (int i = 0; i < 16; i++) {
        int c = lane + 32 * i;
        out[(size_t)row * DM + c] = (v[i] - mean) * inv * lnw[c] + lnb[c];
    }
}

// ---------------------------------------------------------------------------
extern "C" void kernel_launch(void* const* d_in, const int* in_sizes, int n_in,
                              void* d_out, int out_size) {
    const float* x    = (const float*)d_in[0];
    const float* mask = (const float*)d_in[1];
    const float* plog = (const float*)d_in[2];
    const float* Wre  = (const float*)d_in[3];
    const float* Wim  = (const float*)d_in[4];
    const float* bre  = (const float*)d_in[5];
    const float* bim  = (const float*)d_in[6];
    const float* Wor  = (const float*)d_in[7];
    const float* Woi  = (const float*)d_in[8];
    const float* bor  = (const float*)d_in[9];
    // d_in[10] = b_out_im (unused: only real part survives)
    const float* lnw  = (const float*)d_in[11];
    const float* lnb  = (const float*)d_in[12];
    float* out = (float*)d_out;

    const int smem1 = 3 * (128 * 128 + 16384);  // 98304
    cudaFuncSetAttribute(gemm_f16<DM, 1>,
                         cudaFuncAttributeMaxDynamicSharedMemorySize, smem1);
    cudaFuncSetAttribute(gemm_f16<NTOT, 2>,
                         cudaFuncAttributeMaxDynamicSharedMemorySize, smem1);

    // 1: merged conversions + precompute + flag reset
    cvt_all_kernel<<<9217, 256>>>(x, Wre, Wim, Wor, Woi, plog, bre, bim);

    // 2: GEMM1: h = (X @ [Wre/Wim interleaved]^T + b) * gamma  -> g_Hh (fp16)
    gemm_f16<DM, 1><<<dim3(NTOK / 128, NTOT / 128), 128, smem1>>>(nullptr, nullptr);

    // 3: single-pass decoupled-lookback scan (in place on g_Hh)
    scan_onepass<<<BDIM * NCH * 8, 128>>>(mask);

    // 4: GEMM2 (capture slot): y = H @ [Wor,-Woi]^T + b_out_re + x  -> g_y
    gemm_f16<NTOT, 2><<<dim3(NTOK / 128, DM / 128), 128, smem1>>>(bor, x);

    // 5: LayerNorm
    ln_kernel<<<NTOK / 8, 256>>>(lnw, lnb, out);
}